// round 15
// baseline (speedup 1.0000x reference)
#include <cuda_runtime.h>
#include <cuda_fp16.h>
#include <math.h>

#define EPS 1e-5f
#define QK_SCALE 0.17677669529663687f
typedef unsigned int u32;

__device__ float g_table[289];
// fragment-major weight arrays (fp16x2 pairs, hi only), written by conv kernels
__device__ u32 WB1h[65536];   // qk B-frags [h][ks16][nt8][lane32][2]
__device__ u32 WA1h[32768];   // v  A-frags [h][ks16][mt2][lane32][4]
__device__ u32 WA4h[32768];   // out A-frags [ks16][mt16][lane32][4]

// ---------------- compact smem layout (u32 offsets), 2 CTAs/SM ----------------
#define P_X    132
#define O_XH   0        /* 64 x 132 = 8448 */
#define O_AH   8448     /* 64 x 132 = 8448 */
#define O_QKH0 16896    /* 64 x 36  = 2304 */
#define O_QKH1 19200    /* 64 x 36  = 2304 */
#define O_VH0  21504    /* 32 x 36  = 1152 */
#define O_VH1  22656    /* 32 x 36  = 1152 */
#define O_PH   23808    /* 64 x 36  = 2304 */
#define O_TBL  26112    /* 320 */
#define O_BOUT 26432    /* 256 */
#define O_RED  26688    /* 512 */
#define O_MEAN 27200    /* 64  */
#define O_RSTD 27264    /* 64  */
#define O_GW   27328    /* 256 */
#define O_GB   27584    /* 256 */
#define SMEM_U32 27840
#define SMEM_BYTES (SMEM_U32*4)

// ---------------- helpers ----------------
__device__ __forceinline__ u32 pk2(float x0, float x1){
    __half2 h = __floats2half2_rn(x0, x1);   // x0 -> lower half
    return *(u32*)&h;
}
__device__ __forceinline__ void mma16(float* c, const u32* a, const u32* b){
    asm volatile("mma.sync.aligned.m16n8k16.row.col.f32.f16.f16.f32 "
        "{%0,%1,%2,%3},{%4,%5,%6,%7},{%8,%9},{%0,%1,%2,%3};"
        : "+f"(c[0]),"+f"(c[1]),"+f"(c[2]),"+f"(c[3])
        : "r"(a[0]),"r"(a[1]),"r"(a[2]),"r"(a[3]),"r"(b[0]),"r"(b[1]));
}
__device__ __forceinline__ void ldA(u32* a, const u32* s, int r0, int cp_, int pitch, int g, int tg){
    a[0]=s[(r0+g)*pitch+cp_+tg];   a[1]=s[(r0+g+8)*pitch+cp_+tg];
    a[2]=s[(r0+g)*pitch+cp_+tg+4]; a[3]=s[(r0+g+8)*pitch+cp_+tg+4];
}
__device__ __forceinline__ void ldBf(u32* b, const u32* s, int n0, int cp_, int pitch, int g, int tg){
    b[0]=s[(n0+g)*pitch+cp_+tg];   b[1]=s[(n0+g)*pitch+cp_+tg+4];
}

// GEMM1 for one head: per-warp tiles, reads XH + L2 weight frags, writes
// qkh/vh parity-(h&1) buffers. Callable at skewed times per warp group.
__device__ __forceinline__ void gemm1_head(
    u32* su, int h, int lane, int g, int tg,
    int mt, int nb, int vmt, int vnb)
{
    u32* qkh = su + ((h & 1) ? O_QKH1 : O_QKH0);
    u32* vh  = su + ((h & 1) ? O_VH1  : O_VH0);

    float cqh_[4][4], cvh_[2][4];
    #pragma unroll
    for (int i = 0; i < 4; i++)
        #pragma unroll
        for (int q = 0; q < 4; q++) { cqh_[i][q]=0.f; }
    #pragma unroll
    for (int i = 0; i < 2; i++)
        #pragma unroll
        for (int q = 0; q < 4; q++) { cvh_[i][q]=0.f; }

    #pragma unroll 4
    for (int ks = 0; ks < 16; ks++) {
        u32 axh[4];
        ldA(axh, su + O_XH, mt*16, ks*8, P_X, g, tg);
        uint4 awh4 = *(const uint4*)&WA1h[((h*16+ks)*2+vmt)*128 + lane*4];
        #pragma unroll
        for (int nt = 0; nt < 4; nt++) {
            uint2 b2h = *(const uint2*)&WB1h[((h*16+ks)*8+nb+nt)*64 + lane*2];
            u32 bh[2] = {b2h.x, b2h.y};
            mma16(cqh_[nt], axh, bh);   // Xh * Wh
        }
        u32 awh[4] = {awh4.x, awh4.y, awh4.z, awh4.w};
        #pragma unroll
        for (int vt = 0; vt < 2; vt++) {
            u32 bxh[2];
            ldBf(bxh, su + O_XH, (vnb+vt)*8, ks*8, P_X, g, tg);
            mma16(cvh_[vt], awh, bxh);  // Wh * Xh
        }
    }
    // epilogue: q/k transposed pairs (hi only) to parity buffer
    #pragma unroll
    for (int nt = 0; nt < 4; nt++) {
        int isq = (nb + nt) < 4;            // channels < 32 -> q
        float sc = isq ? QK_SCALE : 1.f;
        int col = (nb+nt)*4 + tg, p0 = mt*16 + g;
        qkh[p0*36 + col]     = pk2(cqh_[nt][0]*sc, cqh_[nt][1]*sc);
        qkh[(p0+8)*36 + col] = pk2(cqh_[nt][2]*sc, cqh_[nt][3]*sc);
    }
    #pragma unroll
    for (int vt = 0; vt < 2; vt++) {
        int col = (vnb+vt)*4 + tg, r0 = vmt*16 + g;
        vh[r0*36 + col]     = pk2(cvh_[vt][0], cvh_[vt][1]);
        vh[(r0+8)*36 + col] = pk2(cvh_[vt][2], cvh_[vt][3]);
    }
}

// ---------------- weight precompute: fragment-major fp16 hi layouts ----------------
__global__ void conv_b1(const float* __restrict__ w){
    int b = blockIdx.x;                  // (h*16+ks)*8+nt
    int h = b >> 7, ks = (b >> 3) & 15, nt = b & 7;
    int t = threadIdx.x;                 // lane*2 + j
    int lane = t >> 1, j = t & 1;
    int g = lane >> 2, tg = lane & 3;
    int r = nt*8 + g;
    int R = (r < 32) ? (h*32 + r) : (256 + h*32 + (r - 32));
    int p = ks*8 + tg + j*4;
    WB1h[b*64 + t] = pk2(w[R*256 + 2*p], w[R*256 + 2*p + 1]);
}
__global__ void conv_a1v(const float* __restrict__ w){
    int b = blockIdx.x;                  // (h*16+ks)*2+mt
    int h = b >> 5, mt = b & 1;
    int t = threadIdx.x;                 // lane*4 + j
    int lane = t >> 2, j = t & 3;
    int g = lane >> 2, tg = lane & 3;
    int vrow = mt*16 + g + (j & 1)*8;
    int R = 512 + h*32 + vrow;
    int ks = (b >> 1) & 15;
    int p = ks*8 + tg + (j >> 1)*4;
    WA1h[b*128 + t] = pk2(w[R*256 + 2*p], w[R*256 + 2*p + 1]);
}
__global__ void conv_a4(const float* __restrict__ w){
    int b = blockIdx.x;                  // ks*16 + mt
    int ks = b >> 4, mt = b & 15;
    int t = threadIdx.x;
    int lane = t >> 2, j = t & 3;
    int g = lane >> 2, tg = lane & 3;
    int R = mt*16 + g + (j & 1)*8;
    int p = ks*8 + tg + (j >> 1)*4;
    WA4h[b*128 + t] = pk2(w[R*256 + 2*p], w[R*256 + 2*p + 1]);
}

// ---------------- DPB MLP ----------------
__device__ __forceinline__ float blockreduce64(float v, float* red){
    #pragma unroll
    for (int o = 16; o > 0; o >>= 1) v += __shfl_xor_sync(0xffffffffu, v, o);
    int t = threadIdx.x;
    if ((t & 31) == 0) red[t >> 5] = v;
    __syncthreads();
    float r = red[0] + red[1];
    __syncthreads();
    return r;
}
__global__ void dpb_kernel(
    const float* __restrict__ w1, const float* __restrict__ b1,
    const float* __restrict__ g1, const float* __restrict__ bb1,
    const float* __restrict__ w2, const float* __restrict__ b2,
    const float* __restrict__ g2, const float* __restrict__ bb2,
    const float* __restrict__ w3, const float* __restrict__ b3,
    const float* __restrict__ g3, const float* __restrict__ bb3,
    const float* __restrict__ w4, const float* __restrict__ b4)
{
    __shared__ float hs[64];
    __shared__ float red[2];
    int r = blockIdx.x, j = threadIdx.x;
    float r0 = (float)(r / 17 - 8), r1 = (float)(r % 17 - 8);
    float v = r0 * w1[j] + r1 * w1[64 + j] + b1[j];
    float m = blockreduce64(v, red) * (1.f/64.f);
    float d = v - m;
    float var = blockreduce64(d*d, red) * (1.f/64.f);
    v = fmaxf(d * rsqrtf(var + EPS) * g1[j] + bb1[j], 0.f);
    hs[j] = v; __syncthreads();
    float a = b2[j];
    #pragma unroll 8
    for (int k = 0; k < 64; k++) a += hs[k] * w2[k*64 + j];
    m = blockreduce64(a, red) * (1.f/64.f);
    d = a - m;
    var = blockreduce64(d*d, red) * (1.f/64.f);
    a = fmaxf(d * rsqrtf(var + EPS) * g2[j] + bb2[j], 0.f);
    __syncthreads(); hs[j] = a; __syncthreads();
    a = b3[j];
    #pragma unroll 8
    for (int k = 0; k < 64; k++) a += hs[k] * w3[k*64 + j];
    m = blockreduce64(a, red) * (1.f/64.f);
    d = a - m;
    var = blockreduce64(d*d, red) * (1.f/64.f);
    a = fmaxf(d * rsqrtf(var + EPS) * g3[j] + bb3[j], 0.f);
    __syncthreads(); hs[j] = a; __syncthreads();
    float c = blockreduce64(hs[j] * w4[j], red);
    if (j == 0) g_table[r] = c + b4[0];
}

// ---------------- fused attention (2 CTAs/SM, GEMM1 pipeline-skewed) ----------------
__global__ __launch_bounds__(256, 2) void attn_kernel(
    const float* __restrict__ x, const float* __restrict__ gw, const float* __restrict__ gb,
    const float* __restrict__ b_out, float* __restrict__ out)
{
    extern __shared__ u32 su[];
    float* sf = (float*)su;
    const int t = threadIdx.x, lane = t & 31, w = t >> 5;
    const int g = lane >> 2, tg = lane & 3;
    const int wid = blockIdx.x;
    const int bb = wid >> 10, wh = (wid >> 5) & 31, ww = wid & 31;
    const float* xb = x + ((size_t)bb << 24) + (size_t)(wh * 8) * 256 + ww * 8;

    if (t < 289) sf[O_TBL + t] = g_table[t];
    sf[O_BOUT + t] = b_out[t];
    sf[O_GW + t] = gw[t];
    sf[O_GB + t] = gb[t];

    // ---- LN pass 1: single global read; fp32 stats + pack raw fp16 pairs ----
    {
        int pix = t & 63, q4 = t >> 6;
        const float* xp = xb + (size_t)((pix >> 3) * 256 + (pix & 7))
                             + (size_t)(q4 * 64) * 65536;
        float s = 0.f, ss = 0.f;
        #pragma unroll 4
        for (int j = 0; j < 32; j++) {
            float v0 = xp[(size_t)(2*j)     * 65536];
            float v1 = xp[(size_t)(2*j + 1) * 65536];
            s += v0 + v1; ss += v0*v0 + v1*v1;
            su[O_XH + pix*P_X + q4*32 + j] = pk2(v0, v1);
        }
        sf[O_RED + t] = s; sf[O_RED + 256 + t] = ss;
        __syncthreads();
        if (t < 64) {
            float s0 = sf[O_RED+t] + sf[O_RED+64+t] + sf[O_RED+128+t] + sf[O_RED+192+t];
            float s1 = sf[O_RED+256+t] + sf[O_RED+320+t] + sf[O_RED+384+t] + sf[O_RED+448+t];
            float mn = s0 * (1.f/256.f);
            float vr = s1 * (1.f/256.f) - mn*mn;
            sf[O_MEAN + t] = mn;
            sf[O_RSTD + t] = rsqrtf(vr + EPS);
        }
        __syncthreads();
    }
    // ---- LN pass 2: normalize XH in place (thread-local read/write) ----
    {
        int pix = t & 63, q4 = t >> 6;
        float mn = sf[O_MEAN + pix], rs = sf[O_RSTD + pix];
        #pragma unroll 8
        for (int j = 0; j < 32; j++) {
            int c = q4*64 + 2*j;
            u32 hv = su[O_XH + pix*P_X + q4*32 + j];
            __half2 h2 = *(__half2*)&hv;
            float v0 = (__low2float(h2)  - mn)*rs*sf[O_GW+c]   + sf[O_GB+c];
            float v1 = (__high2float(h2) - mn)*rs*sf[O_GW+c+1] + sf[O_GB+c+1];
            su[O_XH + pix*P_X + q4*32 + j] = pk2(v0, v1);
        }
        __syncthreads();
    }

    const int mt  = w >> 1,  nb  = (w & 1) * 4;   // G1 qk tiles
    const int vmt = w & 1,   vnb = (w >> 1) * 2;  // G1 v tiles
    const int mt3 = w >> 1,  nb3 = (w & 1) * 2;   // GEMM3 tiles

    // prologue: all warps compute GEMM1(0)
    gemm1_head(su, 0, lane, g, tg, mt, nb, vmt, vnb);

    // ---- per-head (GEMM1 skewed one head ahead) ----
    for (int h = 0; h < 8; h++) {
        u32* qkh = su + ((h & 1) ? O_QKH1 : O_QKH0);
        u32* vh  = su + ((h & 1) ? O_VH1  : O_VH0);

        __syncthreads();    // SYNC-A : qkh(h), vh(h) ready

        if (w < 4) {
            // GEMM2 + softmax
            float cs[8][4];
            #pragma unroll
            for (int nt = 0; nt < 8; nt++) {
                int i0 = w*16 + g, i1 = i0 + 8;
                int j0 = nt*8 + 2*tg, j1 = j0 + 1;
                cs[nt][0] = sf[O_TBL + ((i0>>3)-(j0>>3)+7)*15 + (i0&7)-(j0&7)+7];
                cs[nt][1] = sf[O_TBL + ((i0>>3)-(j1>>3)+7)*15 + (i0&7)-(j1&7)+7];
                cs[nt][2] = sf[O_TBL + ((i1>>3)-(j0>>3)+7)*15 + (i1&7)-(j0&7)+7];
                cs[nt][3] = sf[O_TBL + ((i1>>3)-(j1>>3)+7)*15 + (i1&7)-(j1&7)+7];
            }
            #pragma unroll
            for (int ks = 0; ks < 2; ks++) {
                u32 qh[4];
                ldA(qh, qkh, w*16, ks*8, 36, g, tg);
                #pragma unroll
                for (int nt = 0; nt < 8; nt++) {
                    u32 bh[2];
                    ldBf(bh, qkh, nt*8, 16 + ks*8, 36, g, tg);
                    mma16(cs[nt], qh, bh);
                }
            }
            float mx0 = -1e30f, mx1 = -1e30f;
            #pragma unroll
            for (int nt = 0; nt < 8; nt++) {
                mx0 = fmaxf(mx0, fmaxf(cs[nt][0], cs[nt][1]));
                mx1 = fmaxf(mx1, fmaxf(cs[nt][2], cs[nt][3]));
            }
            mx0 = fmaxf(mx0, __shfl_xor_sync(0xffffffffu, mx0, 1));
            mx0 = fmaxf(mx0, __shfl_xor_sync(0xffffffffu, mx0, 2));
            mx1 = fmaxf(mx1, __shfl_xor_sync(0xffffffffu, mx1, 1));
            mx1 = fmaxf(mx1, __shfl_xor_sync(0xffffffffu, mx1, 2));
            float s0 = 0.f, s1 = 0.f;
            #pragma unroll
            for (int nt = 0; nt < 8; nt++) {
                cs[nt][0] = __expf(cs[nt][0] - mx0);
                cs[nt][1] = __expf(cs[nt][1] - mx0);
                cs[nt][2] = __expf(cs[nt][2] - mx1);
                cs[nt][3] = __expf(cs[nt][3] - mx1);
                s0 += cs[nt][0] + cs[nt][1];
                s1 += cs[nt][2] + cs[nt][3];
            }
            s0 += __shfl_xor_sync(0xffffffffu, s0, 1);
            s0 += __shfl_xor_sync(0xffffffffu, s0, 2);
            s1 += __shfl_xor_sync(0xffffffffu, s1, 1);
            s1 += __shfl_xor_sync(0xffffffffu, s1, 2);
            float i0 = 1.f / s0, i1 = 1.f / s1;
            int r0 = w*16 + g;
            #pragma unroll
            for (int nt = 0; nt < 8; nt++) {
                int col = nt*4 + tg;
                su[O_PH + r0*36 + col]     = pk2(cs[nt][0]*i0, cs[nt][1]*i0);
                su[O_PH + (r0+8)*36 + col] = pk2(cs[nt][2]*i1, cs[nt][3]*i1);
            }
        } else if (h < 7) {
            // warps 4-7: fill the softmax window with their GEMM1(h+1) tiles
            gemm1_head(su, h + 1, lane, g, tg, mt, nb, vmt, vnb);
        }
        __syncthreads();    // SYNC-B : PH ready, warps4-7 G1(h+1) done

        // GEMM3: out_h = P @ V  (A = P hi, B = V hi)
        {
            float coh_[2][4];
            #pragma unroll
            for (int i = 0; i < 2; i++)
                #pragma unroll
                for (int q = 0; q < 4; q++) { coh_[i][q]=0.f; }
            #pragma unroll
            for (int ks = 0; ks < 4; ks++) {
                u32 ph_[4];
                ldA(ph_, su + O_PH, mt3*16, ks*8, 36, g, tg);
                #pragma unroll
                for (int nt = 0; nt < 2; nt++) {
                    u32 bh[2];
                    ldBf(bh, vh, (nb3+nt)*8, ks*8, 36, g, tg);
                    mma16(coh_[nt], ph_, bh);
                }
            }
            #pragma unroll
            for (int nt = 0; nt < 2; nt++) {
                int col = h*16 + (nb3+nt)*4 + tg, r0 = mt3*16 + g;
                su[O_AH + r0*P_X + col]     = pk2(coh_[nt][0], coh_[nt][1]);
                su[O_AH + (r0+8)*P_X + col] = pk2(coh_[nt][2], coh_[nt][3]);
            }
        }
        // warps 0-3: their GEMM1(h+1) tiles after GEMM3 (before SYNC-A(h+1))
        if (w < 4 && h < 7)
            gemm1_head(su, h + 1, lane, g, tg, mt, nb, vmt, vnb);
        // no closing barrier: parity buffers + SYNC-A/B ordering make these
        // writes safe vs head-h readers (all drained before SYNC-A/B above).
    }
    __syncthreads();    // AH complete before GEMM4

    // ---- GEMM4: out = Wout @ att  (A = Wh from L2, B = att hi) ----
    {
        float c4[2][8][4];
        #pragma unroll
        for (int m = 0; m < 2; m++)
            #pragma unroll
            for (int nt = 0; nt < 8; nt++)
                c4[m][nt][0]=c4[m][nt][1]=c4[m][nt][2]=c4[m][nt][3]=0.f;

        #pragma unroll 2
        for (int ks = 0; ks < 16; ks++) {
            u32 ah[2][4];
            #pragma unroll
            for (int m = 0; m < 2; m++) {
                uint4 vh4 = *(const uint4*)&WA4h[(ks*16 + (w*2+m))*128 + lane*4];
                ah[m][0]=vh4.x; ah[m][1]=vh4.y; ah[m][2]=vh4.z; ah[m][3]=vh4.w;
            }
            #pragma unroll
            for (int nt = 0; nt < 8; nt++) {
                u32 bh[2];
                ldBf(bh, su + O_AH, nt*8, ks*8, P_X, g, tg);
                #pragma unroll
                for (int m = 0; m < 2; m++) {
                    mma16(c4[m][nt], ah[m], bh);
                }
            }
        }
        // direct global stores: frag (m,nt) covers out rows o0,o0+8, pix nt*8+2tg..+1
        float* ob = out + ((size_t)bb << 24) + (size_t)(wh*8)*256 + ww*8;
        #pragma unroll
        for (int m = 0; m < 2; m++) {
            int o0 = (w*2 + m)*16 + g;
            float b0v = sf[O_BOUT + o0], b1v = sf[O_BOUT + o0 + 8];
            #pragma unroll
            for (int nt = 0; nt < 8; nt++) {
                float2 v0 = make_float2(c4[m][nt][0] + b0v, c4[m][nt][1] + b0v);
                float2 v1 = make_float2(c4[m][nt][2] + b1v, c4[m][nt][3] + b1v);
                *(float2*)&ob[(size_t)o0*65536       + nt*256 + 2*tg] = v0;
                *(float2*)&ob[(size_t)(o0+8)*65536   + nt*256 + 2*tg] = v1;
            }
        }
    }
}

// ---------------- launch ----------------
extern "C" void kernel_launch(void* const* d_in, const int* in_sizes, int n_in,
                              void* d_out, int out_size)
{
    (void)in_sizes; (void)n_in; (void)out_size;
    const float* x     = (const float*)d_in[0];
    const float* g     = (const float*)d_in[1];
    const float* b     = (const float*)d_in[2];
    const float* w_qkv = (const float*)d_in[3];
    const float* w_out = (const float*)d_in[4];
    const float* b_out = (const float*)d_in[5];

    cudaFuncSetAttribute(attn_kernel, cudaFuncAttributeMaxDynamicSharedMemorySize, SMEM_BYTES);

    dpb_kernel<<<289, 64>>>(
        (const float*)d_in[6],  (const float*)d_in[7],
        (const float*)d_in[8],  (const float*)d_in[9],
        (const float*)d_in[10], (const float*)d_in[11],
        (const float*)d_in[12], (const float*)d_in[13],
        (const float*)d_in[14], (const float*)d_in[15],
        (const float*)d_in[16], (const float*)d_in[17],
        (const float*)d_in[18], (const float*)d_in[19]);
    conv_b1<<<1024, 64>>>(w_qkv);
    conv_a1v<<<256, 128>>>(w_qkv);
    conv_a4<<<256, 128>>>(w_out);
    attn_kernel<<<4096, 256, SMEM_BYTES>>>(x, g, b, b_out, (float*)d_out);
}

// round 17
// speedup vs baseline: 1.0948x; 1.0948x over previous
#include <cuda_runtime.h>
#include <cuda_fp16.h>
#include <math.h>

#define EPS 1e-5f
#define QK_SCALE 0.17677669529663687f
typedef unsigned int u32;

__device__ float g_table[289];
// fragment-major weight arrays (fp16x2 pairs, hi only), written by conv_all
__device__ u32 WB1h[65536];   // qk B-frags [h][ks16][nt8][lane32][2]
__device__ u32 WA1h[32768];   // v  A-frags [h][ks16][mt2][lane32][4]
__device__ u32 WA4h[32768];   // out A-frags [ks16][mt16][lane32][4]

// ---------------- compact smem layout (u32 offsets), 2 CTAs/SM ----------------
#define P_X    132
#define O_XH   0        /* 64 x 132 = 8448 */
#define O_AH   8448     /* 64 x 132 = 8448 */
#define O_QKH0 16896    /* 64 x 36  = 2304 */
#define O_QKH1 19200    /* 64 x 36  = 2304 */
#define O_VH0  21504    /* 32 x 36  = 1152 */
#define O_VH1  22656    /* 32 x 36  = 1152 */
#define O_PH   23808    /* 64 x 36  = 2304 */
#define O_TBL  26112    /* 320 */
#define O_BOUT 26432    /* 256 */
#define O_RED  26688    /* 512 */
#define O_MEAN 27200    /* 64  */
#define O_RSTD 27264    /* 64  */
#define O_GW   27328    /* 256 */
#define O_GB   27584    /* 256 */
#define SMEM_U32 27840
#define SMEM_BYTES (SMEM_U32*4)

// ---------------- helpers ----------------
__device__ __forceinline__ u32 pk2(float x0, float x1){
    __half2 h = __floats2half2_rn(x0, x1);   // x0 -> lower half
    return *(u32*)&h;
}
__device__ __forceinline__ void mma16(float* c, const u32* a, const u32* b){
    asm volatile("mma.sync.aligned.m16n8k16.row.col.f32.f16.f16.f32 "
        "{%0,%1,%2,%3},{%4,%5,%6,%7},{%8,%9},{%0,%1,%2,%3};"
        : "+f"(c[0]),"+f"(c[1]),"+f"(c[2]),"+f"(c[3])
        : "r"(a[0]),"r"(a[1]),"r"(a[2]),"r"(a[3]),"r"(b[0]),"r"(b[1]));
}
__device__ __forceinline__ void ldA(u32* a, const u32* s, int r0, int cp_, int pitch, int g, int tg){
    a[0]=s[(r0+g)*pitch+cp_+tg];   a[1]=s[(r0+g+8)*pitch+cp_+tg];
    a[2]=s[(r0+g)*pitch+cp_+tg+4]; a[3]=s[(r0+g+8)*pitch+cp_+tg+4];
}
__device__ __forceinline__ void ldBf(u32* b, const u32* s, int n0, int cp_, int pitch, int g, int tg){
    b[0]=s[(n0+g)*pitch+cp_+tg];   b[1]=s[(n0+g)*pitch+cp_+tg+4];
}

// ---------------- fused weight precompute: all three frag layouts ----------------
__global__ void conv_all(const float* __restrict__ wqkv, const float* __restrict__ wout){
    int blk = blockIdx.x, t = threadIdx.x;
    if (blk < 512) {
        // WB1h: 65536 items, item i -> (b = i>>6, tt = i&63)
        int i = blk*128 + t;
        int b = i >> 6, tt = i & 63;
        int h = b >> 7, ks = (b >> 3) & 15, nt = b & 7;
        int lane = tt >> 1, j = tt & 1;
        int g = lane >> 2, tg = lane & 3;
        int r = nt*8 + g;
        int R = (r < 32) ? (h*32 + r) : (256 + h*32 + (r - 32));
        int p = ks*8 + tg + j*4;
        WB1h[b*64 + tt] = pk2(wqkv[R*256 + 2*p], wqkv[R*256 + 2*p + 1]);
    } else if (blk < 768) {
        // WA1h: block b = blk-512 in 0..255, 128 threads
        int b = blk - 512;
        int h = b >> 5, mt = b & 1;
        int lane = t >> 2, j = t & 3;
        int g = lane >> 2, tg = lane & 3;
        int vrow = mt*16 + g + (j & 1)*8;
        int R = 512 + h*32 + vrow;
        int ks = (b >> 1) & 15;
        int p = ks*8 + tg + (j >> 1)*4;
        WA1h[b*128 + t] = pk2(wqkv[R*256 + 2*p], wqkv[R*256 + 2*p + 1]);
    } else {
        // WA4h: block b = blk-768 in 0..255, 128 threads
        int b = blk - 768;
        int ks = b >> 4, mt = b & 15;
        int lane = t >> 2, j = t & 3;
        int g = lane >> 2, tg = lane & 3;
        int R = mt*16 + g + (j & 1)*8;
        int p = ks*8 + tg + (j >> 1)*4;
        WA4h[b*128 + t] = pk2(wout[R*256 + 2*p], wout[R*256 + 2*p + 1]);
    }
}

// ---------------- DPB MLP ----------------
__device__ __forceinline__ float blockreduce64(float v, float* red){
    #pragma unroll
    for (int o = 16; o > 0; o >>= 1) v += __shfl_xor_sync(0xffffffffu, v, o);
    int t = threadIdx.x;
    if ((t & 31) == 0) red[t >> 5] = v;
    __syncthreads();
    float r = red[0] + red[1];
    __syncthreads();
    return r;
}
__global__ void dpb_kernel(
    const float* __restrict__ w1, const float* __restrict__ b1,
    const float* __restrict__ g1, const float* __restrict__ bb1,
    const float* __restrict__ w2, const float* __restrict__ b2,
    const float* __restrict__ g2, const float* __restrict__ bb2,
    const float* __restrict__ w3, const float* __restrict__ b3,
    const float* __restrict__ g3, const float* __restrict__ bb3,
    const float* __restrict__ w4, const float* __restrict__ b4)
{
    __shared__ float hs[64];
    __shared__ float red[2];
    int r = blockIdx.x, j = threadIdx.x;
    float r0 = (float)(r / 17 - 8), r1 = (float)(r % 17 - 8);
    float v = r0 * w1[j] + r1 * w1[64 + j] + b1[j];
    float m = blockreduce64(v, red) * (1.f/64.f);
    float d = v - m;
    float var = blockreduce64(d*d, red) * (1.f/64.f);
    v = fmaxf(d * rsqrtf(var + EPS) * g1[j] + bb1[j], 0.f);
    hs[j] = v; __syncthreads();
    float a = b2[j];
    #pragma unroll 8
    for (int k = 0; k < 64; k++) a += hs[k] * w2[k*64 + j];
    m = blockreduce64(a, red) * (1.f/64.f);
    d = a - m;
    var = blockreduce64(d*d, red) * (1.f/64.f);
    a = fmaxf(d * rsqrtf(var + EPS) * g2[j] + bb2[j], 0.f);
    __syncthreads(); hs[j] = a; __syncthreads();
    a = b3[j];
    #pragma unroll 8
    for (int k = 0; k < 64; k++) a += hs[k] * w3[k*64 + j];
    m = blockreduce64(a, red) * (1.f/64.f);
    d = a - m;
    var = blockreduce64(d*d, red) * (1.f/64.f);
    a = fmaxf(d * rsqrtf(var + EPS) * g3[j] + bb3[j], 0.f);
    __syncthreads(); hs[j] = a; __syncthreads();
    float c = blockreduce64(hs[j] * w4[j], red);
    if (j == 0) g_table[r] = c + b4[0];
}

// ---------------- fused attention (2 CTAs/SM) ----------------
__global__ __launch_bounds__(256, 2) void attn_kernel(
    const float* __restrict__ x, const float* __restrict__ gw, const float* __restrict__ gb,
    const float* __restrict__ b_out, float* __restrict__ out)
{
    extern __shared__ u32 su[];
    float* sf = (float*)su;
    const int t = threadIdx.x, lane = t & 31, w = t >> 5;
    const int g = lane >> 2, tg = lane & 3;
    const int wid = blockIdx.x;
    const int bb = wid >> 10, wh = (wid >> 5) & 31, ww = wid & 31;
    const float* xb = x + ((size_t)bb << 24) + (size_t)(wh * 8) * 256 + ww * 8;

    if (t < 289) sf[O_TBL + t] = g_table[t];
    sf[O_BOUT + t] = b_out[t];
    sf[O_GW + t] = gw[t];
    sf[O_GB + t] = gb[t];

    // ---- LN pass 1: single global read; fp32 stats + pack raw fp16 pairs ----
    {
        int pix = t & 63, q4 = t >> 6;
        const float* xp = xb + (size_t)((pix >> 3) * 256 + (pix & 7))
                             + (size_t)(q4 * 64) * 65536;
        float s = 0.f, ss = 0.f;
        #pragma unroll 4
        for (int j = 0; j < 32; j++) {
            float v0 = xp[(size_t)(2*j)     * 65536];
            float v1 = xp[(size_t)(2*j + 1) * 65536];
            s += v0 + v1; ss += v0*v0 + v1*v1;
            su[O_XH + pix*P_X + q4*32 + j] = pk2(v0, v1);
        }
        sf[O_RED + t] = s; sf[O_RED + 256 + t] = ss;
        __syncthreads();
        if (t < 64) {
            float s0 = sf[O_RED+t] + sf[O_RED+64+t] + sf[O_RED+128+t] + sf[O_RED+192+t];
            float s1 = sf[O_RED+256+t] + sf[O_RED+320+t] + sf[O_RED+384+t] + sf[O_RED+448+t];
            float mn = s0 * (1.f/256.f);
            float vr = s1 * (1.f/256.f) - mn*mn;
            sf[O_MEAN + t] = mn;
            sf[O_RSTD + t] = rsqrtf(vr + EPS);
        }
        __syncthreads();
    }
    // ---- LN pass 2: normalize XH in place (thread-local read/write) ----
    {
        int pix = t & 63, q4 = t >> 6;
        float mn = sf[O_MEAN + pix], rs = sf[O_RSTD + pix];
        #pragma unroll 8
        for (int j = 0; j < 32; j++) {
            int c = q4*64 + 2*j;
            u32 hv = su[O_XH + pix*P_X + q4*32 + j];
            __half2 h2 = *(__half2*)&hv;
            float v0 = (__low2float(h2)  - mn)*rs*sf[O_GW+c]   + sf[O_GB+c];
            float v1 = (__high2float(h2) - mn)*rs*sf[O_GW+c+1] + sf[O_GB+c+1];
            su[O_XH + pix*P_X + q4*32 + j] = pk2(v0, v1);
        }
        __syncthreads();
    }

    const int mt  = w >> 1,  nb  = (w & 1) * 4;   // G1 qk tiles
    const int vmt = w & 1,   vnb = (w >> 1) * 2;  // G1 v tiles
    const int mt3 = w >> 1,  nb3 = (w & 1) * 2;   // GEMM3 tiles

    // hoisted DPB bias fragments (head-invariant) for warps 0-3
    float bias[8][4];
    if (w < 4) {
        #pragma unroll
        for (int nt = 0; nt < 8; nt++) {
            int i0 = w*16 + g, i1 = i0 + 8;
            int j0 = nt*8 + 2*tg, j1 = j0 + 1;
            bias[nt][0] = sf[O_TBL + ((i0>>3)-(j0>>3)+7)*15 + (i0&7)-(j0&7)+7];
            bias[nt][1] = sf[O_TBL + ((i0>>3)-(j1>>3)+7)*15 + (i0&7)-(j1&7)+7];
            bias[nt][2] = sf[O_TBL + ((i1>>3)-(j0>>3)+7)*15 + (i1&7)-(j0&7)+7];
            bias[nt][3] = sf[O_TBL + ((i1>>3)-(j1>>3)+7)*15 + (i1&7)-(j1&7)+7];
        }
    }

    // ---- per-head ----
    for (int h = 0; h < 8; h++) {
        u32* qkh = su + ((h & 1) ? O_QKH1 : O_QKH0);
        u32* vh  = su + ((h & 1) ? O_VH1  : O_VH0);

        // GEMM1: all single-term fp16 hi (q/k/v)
        float cqh_[4][4], cvh_[2][4];
        #pragma unroll
        for (int i = 0; i < 4; i++)
            #pragma unroll
            for (int q = 0; q < 4; q++) { cqh_[i][q]=0.f; }
        #pragma unroll
        for (int i = 0; i < 2; i++)
            #pragma unroll
            for (int q = 0; q < 4; q++) { cvh_[i][q]=0.f; }

        #pragma unroll 4
        for (int ks = 0; ks < 16; ks++) {
            u32 axh[4];
            ldA(axh, su + O_XH, mt*16, ks*8, P_X, g, tg);
            uint4 awh4 = *(const uint4*)&WA1h[((h*16+ks)*2+vmt)*128 + lane*4];
            #pragma unroll
            for (int nt = 0; nt < 4; nt++) {
                uint2 b2h = *(const uint2*)&WB1h[((h*16+ks)*8+nb+nt)*64 + lane*2];
                u32 bh[2] = {b2h.x, b2h.y};
                mma16(cqh_[nt], axh, bh);   // Xh * Wh
            }
            u32 awh[4] = {awh4.x, awh4.y, awh4.z, awh4.w};
            #pragma unroll
            for (int vt = 0; vt < 2; vt++) {
                u32 bxh[2];
                ldBf(bxh, su + O_XH, (vnb+vt)*8, ks*8, P_X, g, tg);
                mma16(cvh_[vt], awh, bxh);  // Wh * Xh
            }
        }
        // epilogue: q/k transposed pairs (hi only) to parity buffer
        #pragma unroll
        for (int nt = 0; nt < 4; nt++) {
            int isq = (nb + nt) < 4;            // channels < 32 -> q
            float sc = isq ? QK_SCALE : 1.f;
            int col = (nb+nt)*4 + tg, p0 = mt*16 + g;
            qkh[p0*36 + col]     = pk2(cqh_[nt][0]*sc, cqh_[nt][1]*sc);
            qkh[(p0+8)*36 + col] = pk2(cqh_[nt][2]*sc, cqh_[nt][3]*sc);
        }
        #pragma unroll
        for (int vt = 0; vt < 2; vt++) {
            int col = (vnb+vt)*4 + tg, r0 = vmt*16 + g;
            vh[r0*36 + col]     = pk2(cvh_[vt][0], cvh_[vt][1]);
            vh[(r0+8)*36 + col] = pk2(cvh_[vt][2], cvh_[vt][3]);
        }
        __syncthreads();    // SYNC-A

        // GEMM2 + softmax (warps 0..3): single fp16 chain
        if (w < 4) {
            float cs[8][4];
            #pragma unroll
            for (int nt = 0; nt < 8; nt++)
                #pragma unroll
                for (int q = 0; q < 4; q++) cs[nt][q] = bias[nt][q];
            #pragma unroll
            for (int ks = 0; ks < 2; ks++) {
                u32 qh[4];
                ldA(qh, qkh, w*16, ks*8, 36, g, tg);
                #pragma unroll
                for (int nt = 0; nt < 8; nt++) {
                    u32 bh[2];
                    ldBf(bh, qkh, nt*8, 16 + ks*8, 36, g, tg);
                    mma16(cs[nt], qh, bh);
                }
            }
            float mx0 = -1e30f, mx1 = -1e30f;
            #pragma unroll
            for (int nt = 0; nt < 8; nt++) {
                mx0 = fmaxf(mx0, fmaxf(cs[nt][0], cs[nt][1]));
                mx1 = fmaxf(mx1, fmaxf(cs[nt][2], cs[nt][3]));
            }
            mx0 = fmaxf(mx0, __shfl_xor_sync(0xffffffffu, mx0, 1));
            mx0 = fmaxf(mx0, __shfl_xor_sync(0xffffffffu, mx0, 2));
            mx1 = fmaxf(mx1, __shfl_xor_sync(0xffffffffu, mx1, 1));
            mx1 = fmaxf(mx1, __shfl_xor_sync(0xffffffffu, mx1, 2));
            float s0 = 0.f, s1 = 0.f;
            #pragma unroll
            for (int nt = 0; nt < 8; nt++) {
                cs[nt][0] = __expf(cs[nt][0] - mx0);
                cs[nt][1] = __expf(cs[nt][1] - mx0);
                cs[nt][2] = __expf(cs[nt][2] - mx1);
                cs[nt][3] = __expf(cs[nt][3] - mx1);
                s0 += cs[nt][0] + cs[nt][1];
                s1 += cs[nt][2] + cs[nt][3];
            }
            s0 += __shfl_xor_sync(0xffffffffu, s0, 1);
            s0 += __shfl_xor_sync(0xffffffffu, s0, 2);
            s1 += __shfl_xor_sync(0xffffffffu, s1, 1);
            s1 += __shfl_xor_sync(0xffffffffu, s1, 2);
            float i0 = 1.f / s0, i1 = 1.f / s1;
            int r0 = w*16 + g;
            #pragma unroll
            for (int nt = 0; nt < 8; nt++) {
                int col = nt*4 + tg;
                su[O_PH + r0*36 + col]     = pk2(cs[nt][0]*i0, cs[nt][1]*i0);
                su[O_PH + (r0+8)*36 + col] = pk2(cs[nt][2]*i1, cs[nt][3]*i1);
            }
        }
        __syncthreads();    // SYNC-B

        // GEMM3: out_h = P @ V  (A = P hi, B = V hi)
        {
            float coh_[2][4];
            #pragma unroll
            for (int i = 0; i < 2; i++)
                #pragma unroll
                for (int q = 0; q < 4; q++) { coh_[i][q]=0.f; }
            #pragma unroll
            for (int ks = 0; ks < 4; ks++) {
                u32 ph_[4];
                ldA(ph_, su + O_PH, mt3*16, ks*8, 36, g, tg);
                #pragma unroll
                for (int nt = 0; nt < 2; nt++) {
                    u32 bh[2];
                    ldBf(bh, vh, (nb3+nt)*8, ks*8, 36, g, tg);
                    mma16(coh_[nt], ph_, bh);
                }
            }
            #pragma unroll
            for (int nt = 0; nt < 2; nt++) {
                int col = h*16 + (nb3+nt)*4 + tg, r0 = mt3*16 + g;
                su[O_AH + r0*P_X + col]     = pk2(coh_[nt][0], coh_[nt][1]);
                su[O_AH + (r0+8)*P_X + col] = pk2(coh_[nt][2], coh_[nt][3]);
            }
        }
        // no closing barrier: parity buffers + SYNC-A/B ordering make next
        // head's epilogue writes safe vs this head's GEMM2/GEMM3 readers.
    }
    __syncthreads();    // AH complete before GEMM4

    // ---- GEMM4: out = Wout @ att  (A = Wh from L2, B = att hi) ----
    {
        float c4[2][8][4];
        #pragma unroll
        for (int m = 0; m < 2; m++)
            #pragma unroll
            for (int nt = 0; nt < 8; nt++)
                c4[m][nt][0]=c4[m][nt][1]=c4[m][nt][2]=c4[m][nt][3]=0.f;

        #pragma unroll 2
        for (int ks = 0; ks < 16; ks++) {
            u32 ah[2][4];
            #pragma unroll
            for (int m = 0; m < 2; m++) {
                uint4 vh4 = *(const uint4*)&WA4h[(ks*16 + (w*2+m))*128 + lane*4];
                ah[m][0]=vh4.x; ah[m][1]=vh4.y; ah[m][2]=vh4.z; ah[m][3]=vh4.w;
            }
            #pragma unroll
            for (int nt = 0; nt < 8; nt++) {
                u32 bh[2];
                ldBf(bh, su + O_AH, nt*8, ks*8, P_X, g, tg);
                #pragma unroll
                for (int m = 0; m < 2; m++) {
                    mma16(c4[m][nt], ah[m], bh);
                }
            }
        }
        // direct global stores: frag (m,nt) covers out rows o0,o0+8, pix nt*8+2tg..+1
        float* ob = out + ((size_t)bb << 24) + (size_t)(wh*8)*256 + ww*8;
        #pragma unroll
        for (int m = 0; m < 2; m++) {
            int o0 = (w*2 + m)*16 + g;
            float b0v = sf[O_BOUT + o0], b1v = sf[O_BOUT + o0 + 8];
            #pragma unroll
            for (int nt = 0; nt < 8; nt++) {
                float2 v0 = make_float2(c4[m][nt][0] + b0v, c4[m][nt][1] + b0v);
                float2 v1 = make_float2(c4[m][nt][2] + b1v, c4[m][nt][3] + b1v);
                *(float2*)&ob[(size_t)o0*65536       + nt*256 + 2*tg] = v0;
                *(float2*)&ob[(size_t)(o0+8)*65536   + nt*256 + 2*tg] = v1;
            }
        }
    }
}

// ---------------- launch ----------------
extern "C" void kernel_launch(void* const* d_in, const int* in_sizes, int n_in,
                              void* d_out, int out_size)
{
    (void)in_sizes; (void)n_in; (void)out_size;
    const float* x     = (const float*)d_in[0];
    const float* g     = (const float*)d_in[1];
    const float* b     = (const float*)d_in[2];
    const float* w_qkv = (const float*)d_in[3];
    const float* w_out = (const float*)d_in[4];
    const float* b_out = (const float*)d_in[5];

    cudaFuncSetAttribute(attn_kernel, cudaFuncAttributeMaxDynamicSharedMemorySize, SMEM_BYTES);

    dpb_kernel<<<289, 64>>>(
        (const float*)d_in[6],  (const float*)d_in[7],
        (const float*)d_in[8],  (const float*)d_in[9],
        (const float*)d_in[10], (const float*)d_in[11],
        (const float*)d_in[12], (const float*)d_in[13],
        (const float*)d_in[14], (const float*)d_in[15],
        (const float*)d_in[16], (const float*)d_in[17],
        (const float*)d_in[18], (const float*)d_in[19]);
    conv_all<<<1024, 128>>>(w_qkv, w_out);
    attn_kernel<<<4096, 256, SMEM_BYTES>>>(x, g, b, b_out, (float*)d_out);
}